// round 12
// baseline (speedup 1.0000x reference)
#include <cuda_runtime.h>
#include <cuda_fp16.h>
#include <cstdint>

#define HDIM   1024
#define NHEAD  16
#define HEADD  64
#define BATCH  4
#define SEQ    2048
#define BSROWS (BATCH * SEQ)   // 8192

// fp16 scratch (allocation-free rule: __device__ globals)
__device__ __half g_hs16[(size_t)BSROWS * HDIM];
__device__ __half g_wq16[(size_t)HDIM * HDIM];
__device__ __half g_wk16[(size_t)HDIM * HDIM];
__device__ __half g_wv16[(size_t)HDIM * HDIM];
__device__ __half g_wo16[(size_t)HDIM * HDIM];
__device__ __half g_q16[(size_t)BSROWS * HDIM];
__device__ __half g_k16[(size_t)BSROWS * HDIM];
__device__ __half g_v16[(size_t)BSROWS * HDIM];
__device__ __half g_ctx16[(size_t)BSROWS * HDIM];

// ---------------------------------------------------------------------------
// helpers
// ---------------------------------------------------------------------------
__device__ __forceinline__ void mma16(float* c, const unsigned* a, unsigned b0, unsigned b1) {
    asm volatile(
        "mma.sync.aligned.m16n8k16.row.col.f32.f16.f16.f32 "
        "{%0,%1,%2,%3}, {%4,%5,%6,%7}, {%8,%9}, {%0,%1,%2,%3};"
        : "+f"(c[0]), "+f"(c[1]), "+f"(c[2]), "+f"(c[3])
        : "r"(a[0]), "r"(a[1]), "r"(a[2]), "r"(a[3]), "r"(b0), "r"(b1));
}

__device__ __forceinline__ void ldsm4(unsigned* r, unsigned addr) {
    asm volatile("ldmatrix.sync.aligned.m8n8.x4.shared.b16 {%0,%1,%2,%3}, [%4];"
                 : "=r"(r[0]), "=r"(r[1]), "=r"(r[2]), "=r"(r[3]) : "r"(addr));
}

// trans variant: from row-major V (rows=k, cols=n) yields col-major B fragments.
__device__ __forceinline__ void ldsm4t(unsigned* r, unsigned addr) {
    asm volatile("ldmatrix.sync.aligned.m8n8.x4.trans.shared.b16 {%0,%1,%2,%3}, [%4];"
                 : "=r"(r[0]), "=r"(r[1]), "=r"(r[2]), "=r"(r[3]) : "r"(addr));
}

__device__ __forceinline__ float ex2(float x) {
    float r;
    asm("ex2.approx.ftz.f32 %0, %1;" : "=f"(r) : "f"(x));
    return r;
}

// XOR swizzle: 128B logical rows, 16B chunks, chunk ^= (row & 7).
__device__ __forceinline__ int swz(int r, int cbyte) {
    return r * 128 + ((((cbyte >> 4) ^ r) & 7) << 4) + (cbyte & 15);
}

#define CPA(dst, src) \
    asm volatile("cp.async.cg.shared.global [%0], [%1], 16;" :: "r"(dst), "l"(src))
#define CPA_COMMIT() asm volatile("cp.async.commit_group;" ::)
#define CPA_WAIT2()  asm volatile("cp.async.wait_group 2;" ::)
#define CPA_WAIT1()  asm volatile("cp.async.wait_group 1;" ::)
#define CPA_WAIT0()  asm volatile("cp.async.wait_group 0;" ::)

#define ONES2 0x3C003C00u   // half2 {1.0, 1.0} — B fragment for row-sum MMA

__device__ __forceinline__ unsigned h2pack(float lo, float hi) {
    __half2 h = __floats2half2_rn(lo, hi);
    return *(unsigned*)&h;
}

// ---------------------------------------------------------------------------
// fp32 -> fp16 convert
// ---------------------------------------------------------------------------
__global__ void cvt_kernel(const float* __restrict__ s, __half* __restrict__ d, int n4) {
    int stride = gridDim.x * blockDim.x;
    for (int i = blockIdx.x * blockDim.x + threadIdx.x; i < n4; i += stride) {
        float4 v = ((const float4*)s)[i];
        __half2 h0 = __floats2half2_rn(v.x, v.y);
        __half2 h1 = __floats2half2_rn(v.z, v.w);
        ((uint2*)d)[i] = make_uint2(*(unsigned*)&h0, *(unsigned*)&h1);
    }
}

// ---------------------------------------------------------------------------
// fp16 GEMM (unchanged from R9/R10): CTA tile 128x128, 256 threads (8 warps:
// 4M x 2N, warp tile 32x64), 3-stage cp.async, 2 CTAs/SM.
// grid = (N/128, M/128 [, 3]). dyn smem = 98304 B.
// ---------------------------------------------------------------------------
#define GSM 98304

template<bool OUT_HALF>
__device__ __forceinline__ void gemm_core(const __half* __restrict__ A,
                                          const __half* __restrict__ W,
                                          const float* __restrict__ bias,
                                          void* __restrict__ Cv) {
    extern __shared__ __align__(16) char dsm[];   // 3 stages x (A 16KB | B 16KB)
    const int tid = threadIdx.x, lane = tid & 31, wid = tid >> 5;
    const int g = lane >> 2, tg = lane & 3;
    const int wm = wid & 3, wn = wid >> 2;
    const int lrow = lane & 15, lch = lane & 16;
    const size_t bm = (size_t)blockIdx.y * 128, bn = (size_t)blockIdx.x * 128;

    const __half* Ag = A + bm * HDIM;
    const __half* Wg = W + bn * HDIM;
    const unsigned sbase = (unsigned)__cvta_generic_to_shared(dsm);

    float acc[2][8][4] = {};

    auto issue = [&](int kt, int s) {
        unsigned da = sbase + s * 32768, db = da + 16384;
#pragma unroll
        for (int i = 0; i < 4; i++) {
            int idx = tid + 256 * i;            // [0,1024)
            int r = idx >> 3, ch = idx & 7;
            unsigned off = r * 128 + (((ch ^ r) & 7) << 4);
            CPA(da + off, Ag + (size_t)r * HDIM + kt * 64 + ch * 8);
            CPA(db + off, Wg + (size_t)r * HDIM + kt * 64 + ch * 8);
        }
        CPA_COMMIT();
    };

    issue(0, 0); issue(1, 1); issue(2, 2);

    int s = 0;
    for (int kt = 0; kt < 16; kt++) {
        if (kt < 14)      { CPA_WAIT2(); }
        else if (kt == 14){ CPA_WAIT1(); }
        else              { CPA_WAIT0(); }
        __syncthreads();

        const unsigned sa = sbase + s * 32768;
        const unsigned sb = sa + 16384;
#pragma unroll
        for (int ks = 0; ks < 4; ks++) {
            const int cb = ks * 32 + lch;
            unsigned af[2][4], bf[4][4];
            ldsm4(af[0], sa + swz(wm * 32 + lrow,      cb));
            ldsm4(af[1], sa + swz(wm * 32 + 16 + lrow, cb));
#pragma unroll
            for (int np = 0; np < 4; np++)
                ldsm4(bf[np], sb + swz(wn * 64 + np * 16 + lrow, cb));
#pragma unroll
            for (int np = 0; np < 4; np++) {
                mma16(acc[0][2 * np],     af[0], bf[np][0], bf[np][2]);
                mma16(acc[1][2 * np],     af[1], bf[np][0], bf[np][2]);
                mma16(acc[0][2 * np + 1], af[0], bf[np][1], bf[np][3]);
                mma16(acc[1][2 * np + 1], af[1], bf[np][1], bf[np][3]);
            }
        }
        __syncthreads();
        if (kt + 3 < 16) issue(kt + 3, s);
        s = (s == 2) ? 0 : s + 1;
    }

#pragma unroll
    for (int mt = 0; mt < 2; mt++) {
        size_t r0 = bm + wm * 32 + mt * 16 + g;
#pragma unroll
        for (int nt = 0; nt < 8; nt++) {
            size_t n = bn + wn * 64 + nt * 8 + 2 * tg;
            float b0 = bias[n], b1 = bias[n + 1];
            float c0 = acc[mt][nt][0] + b0, c1 = acc[mt][nt][1] + b1;
            float c2 = acc[mt][nt][2] + b0, c3 = acc[mt][nt][3] + b1;
            if (OUT_HALF) {
                __half* C = (__half*)Cv;
                *(__half2*)&C[r0 * HDIM + n]       = __floats2half2_rn(c0, c1);
                *(__half2*)&C[(r0 + 8) * HDIM + n] = __floats2half2_rn(c2, c3);
            } else {
                float* C = (float*)Cv;
                *(float2*)&C[r0 * HDIM + n]       = make_float2(c0, c1);
                *(float2*)&C[(r0 + 8) * HDIM + n] = make_float2(c2, c3);
            }
        }
    }
}

// merged QKV: grid (8, 64, 3); z selects weight/bias/output
__global__ __launch_bounds__(256, 2)
void gemm_qkv(const __half* __restrict__ A,
              const __half* __restrict__ Wq, const __half* __restrict__ Wk,
              const __half* __restrict__ Wv,
              const float* __restrict__ bq, const float* __restrict__ bk,
              const float* __restrict__ bv,
              __half* __restrict__ q, __half* __restrict__ k, __half* __restrict__ v) {
    const int z = blockIdx.z;
    const __half* W = (z == 0) ? Wq : (z == 1) ? Wk : Wv;
    const float* b  = (z == 0) ? bq : (z == 1) ? bk : bv;
    __half* C       = (z == 0) ? q  : (z == 1) ? k  : v;
    gemm_core<true>(A, W, b, C);
}

__global__ __launch_bounds__(256, 2)
void gemm_out(const __half* __restrict__ A, const __half* __restrict__ W,
              const float* __restrict__ bias, float* __restrict__ C) {
    gemm_core<false>(A, W, bias, C);
}

// ---------------------------------------------------------------------------
// Flash attention — R10 math (fixed-reference softmax, fp32 ex2, ones-MMA
// row sums), restructured to 256 threads / 8 warps per CTA (warp tile 16
// q-rows) with __launch_bounds__(256,2): 16 warps/SM (4/SMSP) for latency
// hiding, same as the winning GEMM config. q-tile 128 rows, KV tiles of 64
// (cp.async double buffer). grid = (SEQ/128, NHEAD, BATCH).
// ---------------------------------------------------------------------------
__global__ __launch_bounds__(256, 2)
void attn_h(const __half* __restrict__ q, const __half* __restrict__ k,
            const __half* __restrict__ v, const float* __restrict__ mask,
            __half* __restrict__ ctx) {
    __shared__ __align__(16) __half Ks[2][64 * 64];
    __shared__ __align__(16) __half Vs[2][64 * 64];
    __shared__ __align__(16) float  Msk[2][64];

    const int b = blockIdx.z, h = blockIdx.y, qt = blockIdx.x;
    const int tid = threadIdx.x, lane = tid & 31, wid = tid >> 5;
    const int g = lane >> 2, tg = lane & 3;
    const int lrow = lane & 15, lch = lane & 16;

    const float LOG2E = 1.4426950408889634f;
    const float C1 = 0.125f * LOG2E;    // 1/sqrt(64) * log2(e)
    const float SHIFT = -6.0f;          // fixed exp2 shift; cancels in normalize

    const __half* kbase = k + (size_t)(b * SEQ) * HDIM + h * HEADD;
    const __half* vbase = v + (size_t)(b * SEQ) * HDIM + h * HEADD;
    const float*  mbase = mask + (size_t)b * SEQ;

    const unsigned skb = (unsigned)__cvta_generic_to_shared(Ks);
    const unsigned svb = (unsigned)__cvta_generic_to_shared(Vs);
    const unsigned smb = (unsigned)__cvta_generic_to_shared(Msk);

    auto issue = [&](int kt, int s) {
        unsigned dk = skb + s * 8192, dv = svb + s * 8192;
#pragma unroll
        for (int i = 0; i < 2; i++) {
            int idx = tid + 256 * i;            // [0,512) chunks of 16B
            int r = idx >> 3, ch = idx & 7;
            unsigned off = r * 128 + (((ch ^ r) & 7) << 4);
            CPA(dk + off, kbase + (size_t)(kt * 64 + r) * HDIM + ch * 8);
            CPA(dv + off, vbase + (size_t)(kt * 64 + r) * HDIM + ch * 8);
        }
        if (tid < 16) CPA(smb + s * 256 + tid * 16, mbase + kt * 64 + tid * 4);
        CPA_COMMIT();
    };

    // Q fragments: warp wid owns q-rows [16*wid, 16*wid+16)
    const __half* qp = q + (size_t)(b * SEQ + qt * 128 + wid * 16) * HDIM + h * HEADD;
    unsigned qf[4][4];
#pragma unroll
    for (int ks = 0; ks < 4; ks++) {
        const __half* p = qp + (size_t)g * HDIM + ks * 16 + 2 * tg;
        qf[ks][0] = *(const unsigned*)(p);
        qf[ks][1] = *(const unsigned*)(p + 8 * HDIM);
        qf[ks][2] = *(const unsigned*)(p + 8);
        qf[ks][3] = *(const unsigned*)(p + 8 * HDIM + 8);
    }

    float oacc[8][4] = {};
    float lacc[4] = {};                  // ones-MMA row sums ([0]=row g, [2]=row g+8)

    issue(0, 0);
    for (int kt = 0; kt < SEQ / 64; kt++) {
        if (kt + 1 < SEQ / 64) { issue(kt + 1, (kt + 1) & 1); CPA_WAIT1(); }
        else                   { CPA_WAIT0(); }
        __syncthreads();
        const int s = kt & 1;
        const unsigned sk = skb + s * 8192;
        const unsigned sv = svb + s * 8192;

        // ---- S = Q @ K^T ----
        float sacc[8][4] = {};
#pragma unroll
        for (int ks = 0; ks < 4; ks++) {
            const int cb = ks * 32 + lch;
#pragma unroll
            for (int np = 0; np < 4; np++) {
                unsigned bf[4];
                ldsm4(bf, sk + swz(np * 16 + lrow, cb));
                mma16(sacc[2 * np],     qf[ks], bf[0], bf[2]);
                mma16(sacc[2 * np + 1], qf[ks], bf[1], bf[3]);
            }
        }

        // ---- P = exp2(S*C1 + mask*log2e - 6), no max subtraction ----
        float mk[8][2];
#pragma unroll
        for (int nt = 0; nt < 8; nt++) {
            mk[nt][0] = fmaf(Msk[s][nt * 8 + 2 * tg],     LOG2E, SHIFT);
            mk[nt][1] = fmaf(Msk[s][nt * 8 + 2 * tg + 1], LOG2E, SHIFT);
        }
#pragma unroll
        for (int nt = 0; nt < 8; nt++) {
            sacc[nt][0] = ex2(fmaf(sacc[nt][0], C1, mk[nt][0]));
            sacc[nt][1] = ex2(fmaf(sacc[nt][1], C1, mk[nt][1]));
            sacc[nt][2] = ex2(fmaf(sacc[nt][2], C1, mk[nt][0]));
            sacc[nt][3] = ex2(fmaf(sacc[nt][3], C1, mk[nt][1]));
        }

        // ---- O += P @ V ; l += P @ 1 (both on tensor pipe) ----
#pragma unroll
        for (int ks = 0; ks < 4; ks++) {
            unsigned pf[4];
            pf[0] = h2pack(sacc[2 * ks][0],     sacc[2 * ks][1]);
            pf[1] = h2pack(sacc[2 * ks][2],     sacc[2 * ks][3]);
            pf[2] = h2pack(sacc[2 * ks + 1][0], sacc[2 * ks + 1][1]);
            pf[3] = h2pack(sacc[2 * ks + 1][2], sacc[2 * ks + 1][3]);
            mma16(lacc, pf, ONES2, ONES2);
#pragma unroll
            for (int np = 0; np < 4; np++) {
                unsigned bf[4];
                ldsm4t(bf, sv + swz(ks * 16 + lrow, np * 32 + lch));
                mma16(oacc[2 * np],     pf, bf[0], bf[1]);
                mma16(oacc[2 * np + 1], pf, bf[2], bf[3]);
            }
        }
        __syncthreads();
    }

    // ---- epilogue: O / l -> ctx16 (shift cancels here) ----
    float inv0 = 1.f / lacc[0], inv1 = 1.f / lacc[2];
    size_t r0 = (size_t)(b * SEQ + qt * 128 + wid * 16 + g);
#pragma unroll
    for (int nt = 0; nt < 8; nt++) {
        size_t c = (size_t)(h * HEADD + nt * 8 + 2 * tg);
        *(__half2*)&ctx[r0 * HDIM + c] =
            __floats2half2_rn(oacc[nt][0] * inv0, oacc[nt][1] * inv0);
        *(__half2*)&ctx[(r0 + 8) * HDIM + c] =
            __floats2half2_rn(oacc[nt][2] * inv1, oacc[nt][3] * inv1);
    }
}

// ---------------------------------------------------------------------------
// launch
// ---------------------------------------------------------------------------
extern "C" void kernel_launch(void* const* d_in, const int* in_sizes, int n_in,
                              void* d_out, int out_size) {
    const float* hs   = (const float*)d_in[0];
    const float* mask = (const float*)d_in[1];
    const float* Wq   = (const float*)d_in[2];
    const float* bq   = (const float*)d_in[3];
    const float* Wk   = (const float*)d_in[4];
    const float* bk   = (const float*)d_in[5];
    const float* Wv   = (const float*)d_in[6];
    const float* bv   = (const float*)d_in[7];
    const float* Wo   = (const float*)d_in[8];
    const float* bo   = (const float*)d_in[9];
    float* out = (float*)d_out;

    __half *hs16, *wq16, *wk16, *wv16, *wo16, *q16, *k16, *v16, *ctx16;
    cudaGetSymbolAddress((void**)&hs16,  g_hs16);
    cudaGetSymbolAddress((void**)&wq16,  g_wq16);
    cudaGetSymbolAddress((void**)&wk16,  g_wk16);
    cudaGetSymbolAddress((void**)&wv16,  g_wv16);
    cudaGetSymbolAddress((void**)&wo16,  g_wo16);
    cudaGetSymbolAddress((void**)&q16,   g_q16);
    cudaGetSymbolAddress((void**)&k16,   g_k16);
    cudaGetSymbolAddress((void**)&v16,   g_v16);
    cudaGetSymbolAddress((void**)&ctx16, g_ctx16);

    cudaFuncSetAttribute(gemm_qkv, cudaFuncAttributeMaxDynamicSharedMemorySize, GSM);
    cudaFuncSetAttribute(gemm_out, cudaFuncAttributeMaxDynamicSharedMemorySize, GSM);

    // fp32 -> fp16 converts
    cvt_kernel<<<1024, 256>>>(hs, hs16, BSROWS * HDIM / 4);
    cvt_kernel<<<512, 256>>>(Wq, wq16, HDIM * HDIM / 4);
    cvt_kernel<<<512, 256>>>(Wk, wk16, HDIM * HDIM / 4);
    cvt_kernel<<<512, 256>>>(Wv, wv16, HDIM * HDIM / 4);
    cvt_kernel<<<512, 256>>>(Wo, wo16, HDIM * HDIM / 4);

    // Q, K, V: [8192,1024] = hs @ W^T + b (merged launch)
    dim3 gqkv(HDIM / 128, BSROWS / 128, 3);        // (8, 64, 3)
    gemm_qkv<<<gqkv, 256, GSM>>>(hs16, wq16, wk16, wv16, bq, bk, bv, q16, k16, v16);

    // attention
    dim3 ga(SEQ / 128, NHEAD, BATCH);              // (16, 16, 4)
    attn_h<<<ga, 256>>>(q16, k16, v16, mask, ctx16);

    // out = ctx @ Wo^T + bo (fp32 output)
    dim3 go(HDIM / 128, BSROWS / 128);             // (8, 64)
    gemm_out<<<go, 256, GSM>>>(ctx16, wo16, bo, out);
}

// round 14
// speedup vs baseline: 1.0142x; 1.0142x over previous
#include <cuda_runtime.h>
#include <cuda_fp16.h>
#include <cstdint>

#define HDIM   1024
#define NHEAD  16
#define HEADD  64
#define BATCH  4
#define SEQ    2048
#define BSROWS (BATCH * SEQ)   // 8192

// fp16 scratch (allocation-free rule: __device__ globals)
__device__ __half g_hs16[(size_t)BSROWS * HDIM];
__device__ __half g_wq16[(size_t)HDIM * HDIM];
__device__ __half g_wk16[(size_t)HDIM * HDIM];
__device__ __half g_wv16[(size_t)HDIM * HDIM];
__device__ __half g_wo16[(size_t)HDIM * HDIM];
__device__ __half g_q16[(size_t)BSROWS * HDIM];
__device__ __half g_k16[(size_t)BSROWS * HDIM];
__device__ __half g_v16[(size_t)BSROWS * HDIM];
__device__ __half g_ctx16[(size_t)BSROWS * HDIM];

// ---------------------------------------------------------------------------
// helpers
// ---------------------------------------------------------------------------
__device__ __forceinline__ void mma16(float* c, const unsigned* a, unsigned b0, unsigned b1) {
    asm volatile(
        "mma.sync.aligned.m16n8k16.row.col.f32.f16.f16.f32 "
        "{%0,%1,%2,%3}, {%4,%5,%6,%7}, {%8,%9}, {%0,%1,%2,%3};"
        : "+f"(c[0]), "+f"(c[1]), "+f"(c[2]), "+f"(c[3])
        : "r"(a[0]), "r"(a[1]), "r"(a[2]), "r"(a[3]), "r"(b0), "r"(b1));
}

__device__ __forceinline__ void ldsm4(unsigned* r, unsigned addr) {
    asm volatile("ldmatrix.sync.aligned.m8n8.x4.shared.b16 {%0,%1,%2,%3}, [%4];"
                 : "=r"(r[0]), "=r"(r[1]), "=r"(r[2]), "=r"(r[3]) : "r"(addr));
}

// trans variant: from row-major V (rows=k, cols=n) yields col-major B fragments.
__device__ __forceinline__ void ldsm4t(unsigned* r, unsigned addr) {
    asm volatile("ldmatrix.sync.aligned.m8n8.x4.trans.shared.b16 {%0,%1,%2,%3}, [%4];"
                 : "=r"(r[0]), "=r"(r[1]), "=r"(r[2]), "=r"(r[3]) : "r"(addr));
}

__device__ __forceinline__ float ex2(float x) {
    float r;
    asm("ex2.approx.ftz.f32 %0, %1;" : "=f"(r) : "f"(x));
    return r;
}

// XOR swizzle: 128B logical rows, 16B chunks, chunk ^= (row & 7).
__device__ __forceinline__ int swz(int r, int cbyte) {
    return r * 128 + ((((cbyte >> 4) ^ r) & 7) << 4) + (cbyte & 15);
}

#define CPA(dst, src) \
    asm volatile("cp.async.cg.shared.global [%0], [%1], 16;" :: "r"(dst), "l"(src))
#define CPA_COMMIT() asm volatile("cp.async.commit_group;" ::)
#define CPA_WAIT1()  asm volatile("cp.async.wait_group 1;" ::)
#define CPA_WAIT0()  asm volatile("cp.async.wait_group 0;" ::)

#define ONES2 0x3C003C00u   // half2 {1.0, 1.0} — B fragment for row-sum MMA

__device__ __forceinline__ unsigned h2pack(float lo, float hi) {
    __half2 h = __floats2half2_rn(lo, hi);
    return *(unsigned*)&h;
}

// ---------------------------------------------------------------------------
// fp32 -> fp16 convert
// ---------------------------------------------------------------------------
__global__ void cvt_kernel(const float* __restrict__ s, __half* __restrict__ d, int n4) {
    int stride = gridDim.x * blockDim.x;
    for (int i = blockIdx.x * blockDim.x + threadIdx.x; i < n4; i += stride) {
        float4 v = ((const float4*)s)[i];
        __half2 h0 = __floats2half2_rn(v.x, v.y);
        __half2 h1 = __floats2half2_rn(v.z, v.w);
        ((uint2*)d)[i] = make_uint2(*(unsigned*)&h0, *(unsigned*)&h1);
    }
}

// ---------------------------------------------------------------------------
// fp16 GEMM: CTA tile 128x128, 256 threads (8 warps: 4M x 2N, warp 32x64),
// canonical 3-stage multistage with ONE __syncthreads per k-tile:
//   wait oldest -> sync (retires prev compute on the stage to be refilled)
//   -> issue kt+2 into freed stage -> compute stage kt%3.
// 2 CTAs/SM. grid = (N/128, M/128 [, 3]). dyn smem = 98304 B.
// ---------------------------------------------------------------------------
#define GSM 98304

template<bool OUT_HALF>
__device__ __forceinline__ void gemm_core(const __half* __restrict__ A,
                                          const __half* __restrict__ W,
                                          const float* __restrict__ bias,
                                          void* __restrict__ Cv) {
    extern __shared__ __align__(16) char dsm[];   // 3 stages x (A 16KB | B 16KB)
    const int tid = threadIdx.x, lane = tid & 31, wid = tid >> 5;
    const int g = lane >> 2, tg = lane & 3;
    const int wm = wid & 3, wn = wid >> 2;
    const int lrow = lane & 15, lch = lane & 16;
    const size_t bm = (size_t)blockIdx.y * 128, bn = (size_t)blockIdx.x * 128;

    const __half* Ag = A + bm * HDIM;
    const __half* Wg = W + bn * HDIM;
    const unsigned sbase = (unsigned)__cvta_generic_to_shared(dsm);

    float acc[2][8][4] = {};

    auto issue = [&](int kt, int s) {
        unsigned da = sbase + s * 32768, db = da + 16384;
#pragma unroll
        for (int i = 0; i < 4; i++) {
            int idx = tid + 256 * i;            // [0,1024)
            int r = idx >> 3, ch = idx & 7;
            unsigned off = r * 128 + (((ch ^ r) & 7) << 4);
            CPA(da + off, Ag + (size_t)r * HDIM + kt * 64 + ch * 8);
            CPA(db + off, Wg + (size_t)r * HDIM + kt * 64 + ch * 8);
        }
        CPA_COMMIT();
    };

    issue(0, 0); issue(1, 1);

    int s = 0;
    for (int kt = 0; kt < 16; kt++) {
        if (kt == 15) { CPA_WAIT0(); } else { CPA_WAIT1(); }
        __syncthreads();                       // oldest tile visible; prev stage free
        if (kt + 2 < 16) issue(kt + 2, (kt + 2) % 3);

        const unsigned sa = sbase + s * 32768;
        const unsigned sb = sa + 16384;
#pragma unroll
        for (int ks = 0; ks < 4; ks++) {
            const int cb = ks * 32 + lch;
            unsigned af[2][4], bf[4][4];
            ldsm4(af[0], sa + swz(wm * 32 + lrow,      cb));
            ldsm4(af[1], sa + swz(wm * 32 + 16 + lrow, cb));
#pragma unroll
            for (int np = 0; np < 4; np++)
                ldsm4(bf[np], sb + swz(wn * 64 + np * 16 + lrow, cb));
#pragma unroll
            for (int np = 0; np < 4; np++) {
                mma16(acc[0][2 * np],     af[0], bf[np][0], bf[np][2]);
                mma16(acc[1][2 * np],     af[1], bf[np][0], bf[np][2]);
                mma16(acc[0][2 * np + 1], af[0], bf[np][1], bf[np][3]);
                mma16(acc[1][2 * np + 1], af[1], bf[np][1], bf[np][3]);
            }
        }
        s = (s == 2) ? 0 : s + 1;
    }

#pragma unroll
    for (int mt = 0; mt < 2; mt++) {
        size_t r0 = bm + wm * 32 + mt * 16 + g;
#pragma unroll
        for (int nt = 0; nt < 8; nt++) {
            size_t n = bn + wn * 64 + nt * 8 + 2 * tg;
            float b0 = bias[n], b1 = bias[n + 1];
            float c0 = acc[mt][nt][0] + b0, c1 = acc[mt][nt][1] + b1;
            float c2 = acc[mt][nt][2] + b0, c3 = acc[mt][nt][3] + b1;
            if (OUT_HALF) {
                __half* C = (__half*)Cv;
                *(__half2*)&C[r0 * HDIM + n]       = __floats2half2_rn(c0, c1);
                *(__half2*)&C[(r0 + 8) * HDIM + n] = __floats2half2_rn(c2, c3);
            } else {
                float* C = (float*)Cv;
                *(float2*)&C[r0 * HDIM + n]       = make_float2(c0, c1);
                *(float2*)&C[(r0 + 8) * HDIM + n] = make_float2(c2, c3);
            }
        }
    }
}

// merged QKV: grid (8, 64, 3); z selects weight/bias/output
__global__ __launch_bounds__(256, 2)
void gemm_qkv(const __half* __restrict__ A,
              const __half* __restrict__ Wq, const __half* __restrict__ Wk,
              const __half* __restrict__ Wv,
              const float* __restrict__ bq, const float* __restrict__ bk,
              const float* __restrict__ bv,
              __half* __restrict__ q, __half* __restrict__ k, __half* __restrict__ v) {
    const int z = blockIdx.z;
    const __half* W = (z == 0) ? Wq : (z == 1) ? Wk : Wv;
    const float* b  = (z == 0) ? bq : (z == 1) ? bk : bv;
    __half* C       = (z == 0) ? q  : (z == 1) ? k  : v;
    gemm_core<true>(A, W, b, C);
}

__global__ __launch_bounds__(256, 2)
void gemm_out(const __half* __restrict__ A, const __half* __restrict__ W,
              const float* __restrict__ bias, float* __restrict__ C) {
    gemm_core<false>(A, W, bias, C);
}

// ---------------------------------------------------------------------------
// Flash attention — R10 math (fixed-reference softmax w/ -6 shift, fp32 ex2,
// ones-MMA row sums, P in registers, ldmatrix.trans V), 3-stage single-sync
// KV pipeline. Shared buffers in DYNAMIC smem (49920 B > 48KB static cap):
//   [0, 24576)      K stages (3 x 8192)
//   [24576, 49152)  V stages (3 x 8192)
//   [49152, 49920)  mask stages (3 x 256)
// CTA: 128 threads (4 warps), q-tile 128 rows, KV tiles of 64.
// grid = (SEQ/128, NHEAD, BATCH). 2 CTAs/SM (100KB smem, ~49K regs).
// ---------------------------------------------------------------------------
#define ASM_K 0
#define ASM_V 24576
#define ASM_M 49152
#define ASM_TOTAL 49920

__global__ __launch_bounds__(128, 1)
void attn_h(const __half* __restrict__ q, const __half* __restrict__ k,
            const __half* __restrict__ v, const float* __restrict__ mask,
            __half* __restrict__ ctx) {
    extern __shared__ __align__(16) char asm_buf[];

    const int b = blockIdx.z, h = blockIdx.y, qt = blockIdx.x;
    const int tid = threadIdx.x, lane = tid & 31, wid = tid >> 5;
    const int g = lane >> 2, tg = lane & 3;
    const int lrow = lane & 15, lch = lane & 16;

    const float LOG2E = 1.4426950408889634f;
    const float C1 = 0.125f * LOG2E;    // 1/sqrt(64) * log2(e)
    const float SHIFT = -6.0f;          // fixed exp2 shift; cancels in normalize

    const __half* kbase = k + (size_t)(b * SEQ) * HDIM + h * HEADD;
    const __half* vbase = v + (size_t)(b * SEQ) * HDIM + h * HEADD;
    const float*  mbase = mask + (size_t)b * SEQ;

    const unsigned sb0 = (unsigned)__cvta_generic_to_shared(asm_buf);
    const unsigned skb = sb0 + ASM_K;
    const unsigned svb = sb0 + ASM_V;
    const unsigned smb = sb0 + ASM_M;
    const float* Msk = (const float*)(asm_buf + ASM_M);

    auto issue = [&](int kt, int s) {
        unsigned dk = skb + s * 8192, dv = svb + s * 8192;
#pragma unroll
        for (int i = 0; i < 4; i++) {
            int idx = tid + 128 * i;
            int r = idx >> 3, ch = idx & 7;
            unsigned off = r * 128 + (((ch ^ r) & 7) << 4);
            CPA(dk + off, kbase + (size_t)(kt * 64 + r) * HDIM + ch * 8);
            CPA(dv + off, vbase + (size_t)(kt * 64 + r) * HDIM + ch * 8);
        }
        if (tid < 16) CPA(smb + s * 256 + tid * 16, mbase + kt * 64 + tid * 4);
        CPA_COMMIT();
    };

    // Q fragments: registers for the whole KV loop
    const __half* qp = q + (size_t)(b * SEQ + qt * 128 + wid * 32) * HDIM + h * HEADD;
    unsigned qf[2][4][4];
#pragma unroll
    for (int mt = 0; mt < 2; mt++)
#pragma unroll
        for (int ks = 0; ks < 4; ks++) {
            const __half* p = qp + (size_t)(mt * 16 + g) * HDIM + ks * 16 + 2 * tg;
            qf[mt][ks][0] = *(const unsigned*)(p);
            qf[mt][ks][1] = *(const unsigned*)(p + 8 * HDIM);
            qf[mt][ks][2] = *(const unsigned*)(p + 8);
            qf[mt][ks][3] = *(const unsigned*)(p + 8 * HDIM + 8);
        }

    float oacc[2][8][4] = {};
    float lacc[2][4] = {};               // ones-MMA row sums ([0]=row g, [2]=row g+8)

    issue(0, 0); issue(1, 1);

    int s = 0;
    for (int kt = 0; kt < SEQ / 64; kt++) {
        if (kt == SEQ / 64 - 1) { CPA_WAIT0(); } else { CPA_WAIT1(); }
        __syncthreads();                       // oldest tile visible; prev stage free
        if (kt + 2 < SEQ / 64) issue(kt + 2, (kt + 2) % 3);

        const unsigned sk = skb + s * 8192;
        const unsigned sv = svb + s * 8192;

        // ---- S = Q @ K^T ----
        float sacc[2][8][4] = {};
#pragma unroll
        for (int ks = 0; ks < 4; ks++) {
            const int cb = ks * 32 + lch;
#pragma unroll
            for (int np = 0; np < 4; np++) {
                unsigned bf[4];
                ldsm4(bf, sk + swz(np * 16 + lrow, cb));
                mma16(sacc[0][2 * np],     qf[0][ks], bf[0], bf[2]);
                mma16(sacc[1][2 * np],     qf[1][ks], bf[0], bf[2]);
                mma16(sacc[0][2 * np + 1], qf[0][ks], bf[1], bf[3]);
                mma16(sacc[1][2 * np + 1], qf[1][ks], bf[1], bf[3]);
            }
        }

        // ---- P = exp2(S*C1 + mask*log2e - 6), no max subtraction ----
        float mk[8][2];
#pragma unroll
        for (int nt = 0; nt < 8; nt++) {
            mk[nt][0] = fmaf(Msk[s * 64 + nt * 8 + 2 * tg],     LOG2E, SHIFT);
            mk[nt][1] = fmaf(Msk[s * 64 + nt * 8 + 2 * tg + 1], LOG2E, SHIFT);
        }
#pragma unroll
        for (int mt = 0; mt < 2; mt++)
#pragma unroll
            for (int nt = 0; nt < 8; nt++) {
                sacc[mt][nt][0] = ex2(fmaf(sacc[mt][nt][0], C1, mk[nt][0]));
                sacc[mt][nt][1] = ex2(fmaf(sacc[mt][nt][1], C1, mk[nt][1]));
                sacc[mt][nt][2] = ex2(fmaf(sacc[mt][nt][2], C1, mk[nt][0]));
                sacc[mt][nt][3] = ex2(fmaf(sacc[mt][nt][3], C1, mk[nt][1]));
            }

        // ---- O += P @ V ; l += P @ 1 (both on tensor pipe) ----
#pragma unroll
        for (int ks = 0; ks < 4; ks++) {
            unsigned pf[2][4];
#pragma unroll
            for (int mt = 0; mt < 2; mt++) {
                pf[mt][0] = h2pack(sacc[mt][2 * ks][0],     sacc[mt][2 * ks][1]);
                pf[mt][1] = h2pack(sacc[mt][2 * ks][2],     sacc[mt][2 * ks][3]);
                pf[mt][2] = h2pack(sacc[mt][2 * ks + 1][0], sacc[mt][2 * ks + 1][1]);
                pf[mt][3] = h2pack(sacc[mt][2 * ks + 1][2], sacc[mt][2 * ks + 1][3]);
            }
            mma16(lacc[0], pf[0], ONES2, ONES2);
            mma16(lacc[1], pf[1], ONES2, ONES2);
#pragma unroll
            for (int np = 0; np < 4; np++) {
                unsigned bf[4];
                ldsm4t(bf, sv + swz(ks * 16 + lrow, np * 32 + lch));
                mma16(oacc[0][2 * np],     pf[0], bf[0], bf[1]);
                mma16(oacc[1][2 * np],     pf[1], bf[0], bf[1]);
                mma16(oacc[0][2 * np + 1], pf[0], bf[2], bf[3]);
                mma16(oacc[1][2 * np + 1], pf[1], bf[2], bf[3]);
            }
        }
        s = (s == 2) ? 0 : s + 1;
    }

    // ---- epilogue: O / l -> ctx16 (shift cancels here) ----
#pragma unroll
    for (int mt = 0; mt < 2; mt++) {
        float inv0 = 1.f / lacc[mt][0], inv1 = 1.f / lacc[mt][2];
        size_t r0 = (size_t)(b * SEQ + qt * 128 + wid * 32 + mt * 16 + g);
#pragma unroll
        for (int nt = 0; nt < 8; nt++) {
            size_t c = (size_t)(h * HEADD + nt * 8 + 2 * tg);
            *(__half2*)&ctx[r0 * HDIM + c] =
                __floats2half2_rn(oacc[mt][nt][0] * inv0, oacc[mt][nt][1] * inv0);
            *(__half2*)&ctx[(r0 + 8) * HDIM + c] =
                __floats2half2_rn(oacc[mt][nt][2] * inv1, oacc[mt][nt][3] * inv1);
        }
    }
}

// ---------------------------------------------------------------------------
// launch
// ---------------------------------------------------------------------------
extern "C" void kernel_launch(void* const* d_in, const int* in_sizes, int n_in,
                              void* d_out, int out_size) {
    const float* hs   = (const float*)d_in[0];
    const float* mask = (const float*)d_in[1];
    const float* Wq   = (const float*)d_in[2];
    const float* bq   = (const float*)d_in[3];
    const float* Wk   = (const float*)d_in[4];
    const float* bk   = (const float*)d_in[5];
    const float* Wv   = (const float*)d_in[6];
    const float* bv   = (const float*)d_in[7];
    const float* Wo   = (const float*)d_in[8];
    const float* bo   = (const float*)d_in[9];
    float* out = (float*)d_out;

    __half *hs16, *wq16, *wk16, *wv16, *wo16, *q16, *k16, *v16, *ctx16;
    cudaGetSymbolAddress((void**)&hs16,  g_hs16);
    cudaGetSymbolAddress((void**)&wq16,  g_wq16);
    cudaGetSymbolAddress((void**)&wk16,  g_wk16);
    cudaGetSymbolAddress((void**)&wv16,  g_wv16);
    cudaGetSymbolAddress((void**)&wo16,  g_wo16);
    cudaGetSymbolAddress((void**)&q16,   g_q16);
    cudaGetSymbolAddress((void**)&k16,   g_k16);
    cudaGetSymbolAddress((void**)&v16,   g_v16);
    cudaGetSymbolAddress((void**)&ctx16, g_ctx16);

    cudaFuncSetAttribute(gemm_qkv, cudaFuncAttributeMaxDynamicSharedMemorySize, GSM);
    cudaFuncSetAttribute(gemm_out, cudaFuncAttributeMaxDynamicSharedMemorySize, GSM);
    cudaFuncSetAttribute(attn_h,   cudaFuncAttributeMaxDynamicSharedMemorySize, ASM_TOTAL);

    // fp32 -> fp16 converts
    cvt_kernel<<<1024, 256>>>(hs, hs16, BSROWS * HDIM / 4);
    cvt_kernel<<<512, 256>>>(Wq, wq16, HDIM * HDIM / 4);
    cvt_kernel<<<512, 256>>>(Wk, wk16, HDIM * HDIM / 4);
    cvt_kernel<<<512, 256>>>(Wv, wv16, HDIM * HDIM / 4);
    cvt_kernel<<<512, 256>>>(Wo, wo16, HDIM * HDIM / 4);

    // Q, K, V: [8192,1024] = hs @ W^T + b (merged launch)
    dim3 gqkv(HDIM / 128, BSROWS / 128, 3);        // (8, 64, 3)
    gemm_qkv<<<gqkv, 256, GSM>>>(hs16, wq16, wk16, wv16, bq, bk, bv, q16, k16, v16);

    // attention
    dim3 ga(SEQ / 128, NHEAD, BATCH);              // (16, 16, 4)
    attn_h<<<ga, 128, ASM_TOTAL>>>(q16, k16, v16, mask, ctx16);

    // out = ctx @ Wo^T + bo (fp32 output)
    dim3 go(HDIM / 128, BSROWS / 128);             // (8, 64)
    gemm_out<<<go, 256, GSM>>>(ctx16, wo16, bo, out);
}

// round 15
// speedup vs baseline: 1.0539x; 1.0392x over previous
#include <cuda_runtime.h>
#include <cuda_fp16.h>
#include <cstdint>

#define HDIM   1024
#define NHEAD  16
#define HEADD  64
#define BATCH  4
#define SEQ    2048
#define BSROWS (BATCH * SEQ)   // 8192

// fp16 scratch (allocation-free rule: __device__ globals)
__device__ __half g_hs16[(size_t)BSROWS * HDIM];
__device__ __half g_wq16[(size_t)HDIM * HDIM];
__device__ __half g_wk16[(size_t)HDIM * HDIM];
__device__ __half g_wv16[(size_t)HDIM * HDIM];
__device__ __half g_wo16[(size_t)HDIM * HDIM];
__device__ __half g_q16[(size_t)BSROWS * HDIM];
__device__ __half g_k16[(size_t)BSROWS * HDIM];
__device__ __half g_v16[(size_t)BSROWS * HDIM];
__device__ __half g_ctx16[(size_t)BSROWS * HDIM];

// ---------------------------------------------------------------------------
// helpers
// ---------------------------------------------------------------------------
__device__ __forceinline__ void mma16(float* c, const unsigned* a, unsigned b0, unsigned b1) {
    asm volatile(
        "mma.sync.aligned.m16n8k16.row.col.f32.f16.f16.f32 "
        "{%0,%1,%2,%3}, {%4,%5,%6,%7}, {%8,%9}, {%0,%1,%2,%3};"
        : "+f"(c[0]), "+f"(c[1]), "+f"(c[2]), "+f"(c[3])
        : "r"(a[0]), "r"(a[1]), "r"(a[2]), "r"(a[3]), "r"(b0), "r"(b1));
}

__device__ __forceinline__ void ldsm4(unsigned* r, unsigned addr) {
    asm volatile("ldmatrix.sync.aligned.m8n8.x4.shared.b16 {%0,%1,%2,%3}, [%4];"
                 : "=r"(r[0]), "=r"(r[1]), "=r"(r[2]), "=r"(r[3]) : "r"(addr));
}

// trans variant: from row-major V (rows=k, cols=n) yields col-major B fragments.
__device__ __forceinline__ void ldsm4t(unsigned* r, unsigned addr) {
    asm volatile("ldmatrix.sync.aligned.m8n8.x4.trans.shared.b16 {%0,%1,%2,%3}, [%4];"
                 : "=r"(r[0]), "=r"(r[1]), "=r"(r[2]), "=r"(r[3]) : "r"(addr));
}

__device__ __forceinline__ float ex2(float x) {
    float r;
    asm("ex2.approx.ftz.f32 %0, %1;" : "=f"(r) : "f"(x));
    return r;
}

// XOR swizzle: 128B logical rows, 16B chunks, chunk ^= (row & 7).
__device__ __forceinline__ int swz(int r, int cbyte) {
    return r * 128 + ((((cbyte >> 4) ^ r) & 7) << 4) + (cbyte & 15);
}

#define CPA(dst, src) \
    asm volatile("cp.async.cg.shared.global [%0], [%1], 16;" :: "r"(dst), "l"(src))
#define CPA_COMMIT() asm volatile("cp.async.commit_group;" ::)
#define CPA_WAIT2()  asm volatile("cp.async.wait_group 2;" ::)
#define CPA_WAIT1()  asm volatile("cp.async.wait_group 1;" ::)
#define CPA_WAIT0()  asm volatile("cp.async.wait_group 0;" ::)

#define ONES2 0x3C003C00u   // half2 {1.0, 1.0} — B fragment for row-sum MMA

__device__ __forceinline__ unsigned h2pack(float lo, float hi) {
    __half2 h = __floats2half2_rn(lo, hi);
    return *(unsigned*)&h;
}

// ---------------------------------------------------------------------------
// merged fp32 -> fp16 convert: hs + 4 weights in ONE launch (saves 4 launch
// overheads and keeps DRAM saturated across the whole 72MB span).
// ---------------------------------------------------------------------------
#define HS4 (BSROWS * HDIM / 4)   // 2097152
#define W4  (HDIM * HDIM / 4)     // 262144 = 1<<18

__global__ void cvt_all(const float* __restrict__ hs,
                        const float* __restrict__ Wq, const float* __restrict__ Wk,
                        const float* __restrict__ Wv, const float* __restrict__ Wo,
                        __half* __restrict__ dhs,
                        __half* __restrict__ dwq, __half* __restrict__ dwk,
                        __half* __restrict__ dwv, __half* __restrict__ dwo) {
    const int total = HS4 + 4 * W4;
    const int stride = gridDim.x * blockDim.x;
    for (int i = blockIdx.x * blockDim.x + threadIdx.x; i < total; i += stride) {
        const float* s; __half* d; int j;
        if (i < HS4) { s = hs; d = dhs; j = i; }
        else {
            int t = i - HS4, w = t >> 18;
            j = t & (W4 - 1);
            if (w == 0)      { s = Wq; d = dwq; }
            else if (w == 1) { s = Wk; d = dwk; }
            else if (w == 2) { s = Wv; d = dwv; }
            else             { s = Wo; d = dwo; }
        }
        float4 v = ((const float4*)s)[j];
        __half2 h0 = __floats2half2_rn(v.x, v.y);
        __half2 h1 = __floats2half2_rn(v.z, v.w);
        ((uint2*)d)[j] = make_uint2(*(unsigned*)&h0, *(unsigned*)&h1);
    }
}

// ---------------------------------------------------------------------------
// fp16 GEMM (R10 exact): CTA tile 128x128, 256 threads (8 warps: 4M x 2N,
// warp tile 32x64), 3-stage cp.async with two syncs per tile, 2 CTAs/SM.
// grid = (N/128, M/128 [, 3]). dyn smem = 98304 B.
// ---------------------------------------------------------------------------
#define GSM 98304

template<bool OUT_HALF>
__device__ __forceinline__ void gemm_core(const __half* __restrict__ A,
                                          const __half* __restrict__ W,
                                          const float* __restrict__ bias,
                                          void* __restrict__ Cv) {
    extern __shared__ __align__(16) char dsm[];   // 3 stages x (A 16KB | B 16KB)
    const int tid = threadIdx.x, lane = tid & 31, wid = tid >> 5;
    const int g = lane >> 2, tg = lane & 3;
    const int wm = wid & 3, wn = wid >> 2;
    const int lrow = lane & 15, lch = lane & 16;
    const size_t bm = (size_t)blockIdx.y * 128, bn = (size_t)blockIdx.x * 128;

    const __half* Ag = A + bm * HDIM;
    const __half* Wg = W + bn * HDIM;
    const unsigned sbase = (unsigned)__cvta_generic_to_shared(dsm);

    float acc[2][8][4] = {};

    auto issue = [&](int kt, int s) {
        unsigned da = sbase + s * 32768, db = da + 16384;
#pragma unroll
        for (int i = 0; i < 4; i++) {
            int idx = tid + 256 * i;            // [0,1024)
            int r = idx >> 3, ch = idx & 7;
            unsigned off = r * 128 + (((ch ^ r) & 7) << 4);
            CPA(da + off, Ag + (size_t)r * HDIM + kt * 64 + ch * 8);
            CPA(db + off, Wg + (size_t)r * HDIM + kt * 64 + ch * 8);
        }
        CPA_COMMIT();
    };

    issue(0, 0); issue(1, 1); issue(2, 2);

    int s = 0;
    for (int kt = 0; kt < 16; kt++) {
        if (kt < 14)      { CPA_WAIT2(); }
        else if (kt == 14){ CPA_WAIT1(); }
        else              { CPA_WAIT0(); }
        __syncthreads();

        const unsigned sa = sbase + s * 32768;
        const unsigned sb = sa + 16384;
#pragma unroll
        for (int ks = 0; ks < 4; ks++) {
            const int cb = ks * 32 + lch;
            unsigned af[2][4], bf[4][4];
            ldsm4(af[0], sa + swz(wm * 32 + lrow,      cb));
            ldsm4(af[1], sa + swz(wm * 32 + 16 + lrow, cb));
#pragma unroll
            for (int np = 0; np < 4; np++)
                ldsm4(bf[np], sb + swz(wn * 64 + np * 16 + lrow, cb));
#pragma unroll
            for (int np = 0; np < 4; np++) {
                mma16(acc[0][2 * np],     af[0], bf[np][0], bf[np][2]);
                mma16(acc[1][2 * np],     af[1], bf[np][0], bf[np][2]);
                mma16(acc[0][2 * np + 1], af[0], bf[np][1], bf[np][3]);
                mma16(acc[1][2 * np + 1], af[1], bf[np][1], bf[np][3]);
            }
        }
        __syncthreads();
        if (kt + 3 < 16) issue(kt + 3, s);
        s = (s == 2) ? 0 : s + 1;
    }

#pragma unroll
    for (int mt = 0; mt < 2; mt++) {
        size_t r0 = bm + wm * 32 + mt * 16 + g;
#pragma unroll
        for (int nt = 0; nt < 8; nt++) {
            size_t n = bn + wn * 64 + nt * 8 + 2 * tg;
            float b0 = bias[n], b1 = bias[n + 1];
            float c0 = acc[mt][nt][0] + b0, c1 = acc[mt][nt][1] + b1;
            float c2 = acc[mt][nt][2] + b0, c3 = acc[mt][nt][3] + b1;
            if (OUT_HALF) {
                __half* C = (__half*)Cv;
                *(__half2*)&C[r0 * HDIM + n]       = __floats2half2_rn(c0, c1);
                *(__half2*)&C[(r0 + 8) * HDIM + n] = __floats2half2_rn(c2, c3);
            } else {
                float* C = (float*)Cv;
                *(float2*)&C[r0 * HDIM + n]       = make_float2(c0, c1);
                *(float2*)&C[(r0 + 8) * HDIM + n] = make_float2(c2, c3);
            }
        }
    }
}

// merged QKV: grid (8, 64, 3); z selects weight/bias/output
__global__ __launch_bounds__(256, 2)
void gemm_qkv(const __half* __restrict__ A,
              const __half* __restrict__ Wq, const __half* __restrict__ Wk,
              const __half* __restrict__ Wv,
              const float* __restrict__ bq, const float* __restrict__ bk,
              const float* __restrict__ bv,
              __half* __restrict__ q, __half* __restrict__ k, __half* __restrict__ v) {
    const int z = blockIdx.z;
    const __half* W = (z == 0) ? Wq : (z == 1) ? Wk : Wv;
    const float* b  = (z == 0) ? bq : (z == 1) ? bk : bv;
    __half* C       = (z == 0) ? q  : (z == 1) ? k  : v;
    gemm_core<true>(A, W, b, C);
}

__global__ __launch_bounds__(256, 2)
void gemm_out(const __half* __restrict__ A, const __half* __restrict__ W,
              const float* __restrict__ bias, float* __restrict__ C) {
    gemm_core<false>(A, W, bias, C);
}

// ---------------------------------------------------------------------------
// Flash attention (R10 exact) — fixed-reference softmax with -6 shift folded
// into the mask addend, fp32 ex2, ones-MMA row sums, P in registers,
// ldmatrix.trans V. CTA: 128 threads (4 warps), q-tile 128 rows, KV tiles
// of 64 (cp.async double buffer). grid = (SEQ/128, NHEAD, BATCH).
// ---------------------------------------------------------------------------
__global__ __launch_bounds__(128, 1)
void attn_h(const __half* __restrict__ q, const __half* __restrict__ k,
            const __half* __restrict__ v, const float* __restrict__ mask,
            __half* __restrict__ ctx) {
    __shared__ __align__(16) __half Ks[2][64 * 64];
    __shared__ __align__(16) __half Vs[2][64 * 64];
    __shared__ __align__(16) float  Msk[2][64];

    const int b = blockIdx.z, h = blockIdx.y, qt = blockIdx.x;
    const int tid = threadIdx.x, lane = tid & 31, wid = tid >> 5;
    const int g = lane >> 2, tg = lane & 3;
    const int lrow = lane & 15, lch = lane & 16;

    const float LOG2E = 1.4426950408889634f;
    const float C1 = 0.125f * LOG2E;    // 1/sqrt(64) * log2(e)
    const float SHIFT = -6.0f;          // fixed exp2 shift; cancels in normalize

    const __half* kbase = k + (size_t)(b * SEQ) * HDIM + h * HEADD;
    const __half* vbase = v + (size_t)(b * SEQ) * HDIM + h * HEADD;
    const float*  mbase = mask + (size_t)b * SEQ;

    const unsigned skb = (unsigned)__cvta_generic_to_shared(Ks);
    const unsigned svb = (unsigned)__cvta_generic_to_shared(Vs);
    const unsigned smb = (unsigned)__cvta_generic_to_shared(Msk);

    auto issue = [&](int kt, int s) {
        unsigned dk = skb + s * 8192, dv = svb + s * 8192;
#pragma unroll
        for (int i = 0; i < 4; i++) {
            int idx = tid + 128 * i;
            int r = idx >> 3, ch = idx & 7;
            unsigned off = r * 128 + (((ch ^ r) & 7) << 4);
            CPA(dk + off, kbase + (size_t)(kt * 64 + r) * HDIM + ch * 8);
            CPA(dv + off, vbase + (size_t)(kt * 64 + r) * HDIM + ch * 8);
        }
        if (tid < 16) CPA(smb + s * 256 + tid * 16, mbase + kt * 64 + tid * 4);
        CPA_COMMIT();
    };

    // Q fragments: registers for the whole KV loop
    const __half* qp = q + (size_t)(b * SEQ + qt * 128 + wid * 32) * HDIM + h * HEADD;
    unsigned qf[2][4][4];
#pragma unroll
    for (int mt = 0; mt < 2; mt++)
#pragma unroll
        for (int ks = 0; ks < 4; ks++) {
            const __half* p = qp + (size_t)(mt * 16 + g) * HDIM + ks * 16 + 2 * tg;
            qf[mt][ks][0] = *(const unsigned*)(p);
            qf[mt][ks][1] = *(const unsigned*)(p + 8 * HDIM);
            qf[mt][ks][2] = *(const unsigned*)(p + 8);
            qf[mt][ks][3] = *(const unsigned*)(p + 8 * HDIM + 8);
        }

    float oacc[2][8][4] = {};
    float lacc[2][4] = {};               // ones-MMA row sums ([0]=row g, [2]=row g+8)

    issue(0, 0);
    for (int kt = 0; kt < SEQ / 64; kt++) {
        if (kt + 1 < SEQ / 64) { issue(kt + 1, (kt + 1) & 1); CPA_WAIT1(); }
        else                   { CPA_WAIT0(); }
        __syncthreads();
        const int s = kt & 1;
        const unsigned sk = skb + s * 8192;
        const unsigned sv = svb + s * 8192;

        // ---- S = Q @ K^T ----
        float sacc[2][8][4] = {};
#pragma unroll
        for (int ks = 0; ks < 4; ks++) {
            const int cb = ks * 32 + lch;
#pragma unroll
            for (int np = 0; np < 4; np++) {
                unsigned bf[4];
                ldsm4(bf, sk + swz(np * 16 + lrow, cb));
                mma16(sacc[0][2 * np],     qf[0][ks], bf[0], bf[2]);
                mma16(sacc[1][2 * np],     qf[1][ks], bf[0], bf[2]);
                mma16(sacc[0][2 * np + 1], qf[0][ks], bf[1], bf[3]);
                mma16(sacc[1][2 * np + 1], qf[1][ks], bf[1], bf[3]);
            }
        }

        // ---- P = exp2(S*C1 + mask*log2e - 6), no max subtraction ----
        float mk[8][2];
#pragma unroll
        for (int nt = 0; nt < 8; nt++) {
            mk[nt][0] = fmaf(Msk[s][nt * 8 + 2 * tg],     LOG2E, SHIFT);
            mk[nt][1] = fmaf(Msk[s][nt * 8 + 2 * tg + 1], LOG2E, SHIFT);
        }
#pragma unroll
        for (int mt = 0; mt < 2; mt++)
#pragma unroll
            for (int nt = 0; nt < 8; nt++) {
                sacc[mt][nt][0] = ex2(fmaf(sacc[mt][nt][0], C1, mk[nt][0]));
                sacc[mt][nt][1] = ex2(fmaf(sacc[mt][nt][1], C1, mk[nt][1]));
                sacc[mt][nt][2] = ex2(fmaf(sacc[mt][nt][2], C1, mk[nt][0]));
                sacc[mt][nt][3] = ex2(fmaf(sacc[mt][nt][3], C1, mk[nt][1]));
            }

        // ---- O += P @ V ; l += P @ 1 (both on tensor pipe) ----
#pragma unroll
        for (int ks = 0; ks < 4; ks++) {
            unsigned pf[2][4];
#pragma unroll
            for (int mt = 0; mt < 2; mt++) {
                pf[mt][0] = h2pack(sacc[mt][2 * ks][0],     sacc[mt][2 * ks][1]);
                pf[mt][1] = h2pack(sacc[mt][2 * ks][2],     sacc[mt][2 * ks][3]);
                pf[mt][2] = h2pack(sacc[mt][2 * ks + 1][0], sacc[mt][2 * ks + 1][1]);
                pf[mt][3] = h2pack(sacc[mt][2 * ks + 1][2], sacc[mt][2 * ks + 1][3]);
            }
            mma16(lacc[0], pf[0], ONES2, ONES2);
            mma16(lacc[1], pf[1], ONES2, ONES2);
#pragma unroll
            for (int np = 0; np < 4; np++) {
                unsigned bf[4];
                ldsm4t(bf, sv + swz(ks * 16 + lrow, np * 32 + lch));
                mma16(oacc[0][2 * np],     pf[0], bf[0], bf[1]);
                mma16(oacc[1][2 * np],     pf[1], bf[0], bf[1]);
                mma16(oacc[0][2 * np + 1], pf[0], bf[2], bf[3]);
                mma16(oacc[1][2 * np + 1], pf[1], bf[2], bf[3]);
            }
        }
        __syncthreads();
    }

    // ---- epilogue: O / l -> ctx16 (shift cancels here) ----
#pragma unroll
    for (int mt = 0; mt < 2; mt++) {
        float inv0 = 1.f / lacc[mt][0], inv1 = 1.f / lacc[mt][2];
        size_t r0 = (size_t)(b * SEQ + qt * 128 + wid * 32 + mt * 16 + g);
#pragma unroll
        for (int nt = 0; nt < 8; nt++) {
            size_t c = (size_t)(h * HEADD + nt * 8 + 2 * tg);
            *(__half2*)&ctx[r0 * HDIM + c] =
                __floats2half2_rn(oacc[mt][nt][0] * inv0, oacc[mt][nt][1] * inv0);
            *(__half2*)&ctx[(r0 + 8) * HDIM + c] =
                __floats2half2_rn(oacc[mt][nt][2] * inv1, oacc[mt][nt][3] * inv1);
        }
    }
}

// ---------------------------------------------------------------------------
// launch
// ---------------------------------------------------------------------------
extern "C" void kernel_launch(void* const* d_in, const int* in_sizes, int n_in,
                              void* d_out, int out_size) {
    const float* hs   = (const float*)d_in[0];
    const float* mask = (const float*)d_in[1];
    const float* Wq   = (const float*)d_in[2];
    const float* bq   = (const float*)d_in[3];
    const float* Wk   = (const float*)d_in[4];
    const float* bk   = (const float*)d_in[5];
    const float* Wv   = (const float*)d_in[6];
    const float* bv   = (const float*)d_in[7];
    const float* Wo   = (const float*)d_in[8];
    const float* bo   = (const float*)d_in[9];
    float* out = (float*)d_out;

    __half *hs16, *wq16, *wk16, *wv16, *wo16, *q16, *k16, *v16, *ctx16;
    cudaGetSymbolAddress((void**)&hs16,  g_hs16);
    cudaGetSymbolAddress((void**)&wq16,  g_wq16);
    cudaGetSymbolAddress((void**)&wk16,  g_wk16);
    cudaGetSymbolAddress((void**)&wv16,  g_wv16);
    cudaGetSymbolAddress((void**)&wo16,  g_wo16);
    cudaGetSymbolAddress((void**)&q16,   g_q16);
    cudaGetSymbolAddress((void**)&k16,   g_k16);
    cudaGetSymbolAddress((void**)&v16,   g_v16);
    cudaGetSymbolAddress((void**)&ctx16, g_ctx16);

    cudaFuncSetAttribute(gemm_qkv, cudaFuncAttributeMaxDynamicSharedMemorySize, GSM);
    cudaFuncSetAttribute(gemm_out, cudaFuncAttributeMaxDynamicSharedMemorySize, GSM);

    // merged fp32 -> fp16 converts (one launch, big grid)
    cvt_all<<<2048, 256>>>(hs, Wq, Wk, Wv, Wo, hs16, wq16, wk16, wv16, wo16);

    // Q, K, V: [8192,1024] = hs @ W^T + b (merged launch)
    dim3 gqkv(HDIM / 128, BSROWS / 128, 3);        // (8, 64, 3)
    gemm_qkv<<<gqkv, 256, GSM>>>(hs16, wq16, wk16, wv16, bq, bk, bv, q16, k16, v16);

    // attention
    dim3 ga(SEQ / 128, NHEAD, BATCH);              // (16, 16, 4)
    attn_h<<<ga, 128>>>(q16, k16, v16, mask, ctx16);

    // out = ctx @ Wo^T + bo (fp32 output)
    dim3 go(HDIM / 128, BSROWS / 128);             // (8, 64)
    gemm_out<<<go, 256, GSM>>>(ctx16, wo16, bo, out);
}